// round 7
// baseline (speedup 1.0000x reference)
#include <cuda_runtime.h>
#include <cuda_bf16.h>
#include <cstdint>

#define BB 256
#define TT 512
#define NS 256
#define START_TAG 254
#define STOP_TAG 255
#define LN2F 0.6931471805599453f
#define NB 8
#define NCTA (BB / NB)
#define RSB 528           // ea row stride bytes (132 words -> conflict-free B loads)
#define EABUF (NB * RSB)  // 4224

// scratch (allocation-free rule: __device__ globals)
__device__ float g_den[BB];
__device__ float g_num[BB];
// E = exp(trans) bf16, columns PRE-PERMUTED: g_Ebf[r*256+x] = exp(trans[r][perm(x)])
// perm(x) = 32*(x>>5) + ((x>>2)&7) + 8*(x&3)
__device__ unsigned short g_Ebf[NS * NS];

__device__ __forceinline__ int permf(int x) {
    return 32 * (x >> 5) + ((x >> 2) & 7) + 8 * (x & 3);
}
__device__ __forceinline__ int iperm(int s) {
    return 32 * (s >> 5) + 4 * (s & 7) + ((s >> 3) & 3);
}

// ---------------------------------------------------------------------------
// smem layout (static, ~10.7 KB)
// ---------------------------------------------------------------------------
#define SM_EA    0        // 2 x 4224 ea double buffer: [n][x] bf16 (permuted states)
#define SM_MSLOT 8448     // 2 x 8 floats (state-0 value per batch, renorm probe)
#define SM_MASK  8512     // 512 u32 mask bitfields
#define SM_C0    10560    // 8 floats
#define SM_RED   10592    // 64 floats
#define SM_KS    10848    // 8 ints
#define SM_SS    10880    // 8 floats
#define SM_TOTAL 10912

#define MMA_BF16(d, a, b0, b1) \
    asm volatile( \
        "mma.sync.aligned.m16n8k16.row.col.f32.bf16.bf16.f32 " \
        "{%0,%1,%2,%3},{%4,%5,%6,%7},{%8,%9},{%0,%1,%2,%3};" \
        : "+f"((d)[0]), "+f"((d)[1]), "+f"((d)[2]), "+f"((d)[3]) \
        : "r"((a)[0]), "r"((a)[1]), "r"((a)[2]), "r"((a)[3]), "r"(b0), "r"(b1))

// ---------------------------------------------------------------------------
// Prep: permuted bf16 E
// ---------------------------------------------------------------------------
__global__ void prep_kernel(const float* __restrict__ trans) {
    int gid = blockIdx.x * blockDim.x + threadIdx.x;  // 0..65535
    int r = gid >> 8, x = gid & 255;
    g_Ebf[gid] = __bfloat16_as_ushort(__float2bfloat16(__expf(trans[r * NS + permf(x)])));
}

// ---------------------------------------------------------------------------
// Forward recursion via mma.sync bf16, linear space + stale pow2 renorm.
// ---------------------------------------------------------------------------
__global__ void __launch_bounds__(256, 1) forward_kernel(
    const float* __restrict__ inputs,
    const float* __restrict__ trans,
    const int* __restrict__ mask)
{
    __shared__ __align__(16) char smem[SM_TOTAL];
    const uint32_t smem_base = (uint32_t)__cvta_generic_to_shared(smem);
    float*    mslotF = (float*)(smem + SM_MSLOT);
    uint32_t* masksS = (uint32_t*)(smem + SM_MASK);
    float*    C0sm   = (float*)(smem + SM_C0);
    float*    redsm  = (float*)(smem + SM_RED);
    int*      kssm   = (int*)(smem + SM_KS);
    float*    Ssm    = (float*)(smem + SM_SS);

    const int tid  = threadIdx.x;
    const int lane = tid & 31;
    const int wid  = tid >> 5;
    const int gidr = lane >> 2;   // groupID
    const int tig  = lane & 3;    // thread-in-group
    const int wbase = wid * 32;   // warp's state base
    const int bb    = blockIdx.x * NB;
    const int n0 = 2 * tig, n1 = n0 + 1;

    // mask bitfields
    for (int tt = tid; tt < TT; tt += 256) {
        uint32_t w = 0;
#pragma unroll
        for (int n = 0; n < NB; n++) w |= (mask[(bb + n) * TT + tt] ? 1u : 0u) << n;
        masksS[tt] = w;
    }

    // A fragments from permuted E (128 u32/thread, resident)
    uint32_t A[2][16][4];
    {
#pragma unroll
        for (int mt = 0; mt < 2; mt++) {
            int r0 = wbase + mt * 16 + gidr, r1 = r0 + 8;
#pragma unroll
            for (int kt = 0; kt < 16; kt++) {
                int c0 = kt * 16 + tig * 2;
                A[mt][kt][0] = *(const uint32_t*)&g_Ebf[r0 * NS + c0];
                A[mt][kt][1] = *(const uint32_t*)&g_Ebf[r1 * NS + c0];
                A[mt][kt][2] = *(const uint32_t*)&g_Ebf[r0 * NS + c0 + 8];
                A[mt][kt][3] = *(const uint32_t*)&g_Ebf[r1 * NS + c0 + 8];
            }
        }
    }

    // alpha0: per-batch max -> C0; ea0 at physical iperm(state)
    {
        float a0v[NB];
        float tS = trans[tid * NS + START_TAG];
#pragma unroll
        for (int n = 0; n < NB; n++)
            a0v[n] = tS + inputs[((size_t)(bb + n) * TT) * NS + tid];
#pragma unroll
        for (int n = 0; n < NB; n++) {
            float m = a0v[n];
#pragma unroll
            for (int o = 16; o; o >>= 1) m = fmaxf(m, __shfl_xor_sync(~0u, m, o));
            if (lane == 0) redsm[wid * 8 + n] = m;
        }
        __syncthreads();
        if (tid < 8) {
            float m = -INFINITY;
#pragma unroll
            for (int w = 0; w < 8; w++) m = fmaxf(m, redsm[w * 8 + tid]);
            C0sm[tid] = m;
        }
        __syncthreads();
        int xph = iperm(tid);
#pragma unroll
        for (int n = 0; n < NB; n++) {
            float e = __expf(a0v[n] - C0sm[n]);
            unsigned short h = __bfloat16_as_ushort(__float2bfloat16(e));
            uint32_t ad = smem_base + SM_EA + (uint32_t)(n * RSB + xph * 2);
            asm volatile("st.shared.b16 [%0], %1;" :: "r"(ad), "h"(h));
            if (tid == 0) mslotF[n] = e;
        }
        __syncthreads();
    }

    // emission pointers (states m00..m11 logical)
    const float* pn0 = inputs + (size_t)(bb + n0) * TT * NS;
    const float* pn1 = inputs + (size_t)(bb + n1) * TT * NS;
    const int m00 = wbase + gidr, m01 = m00 + 8, m10 = m00 + 16, m11 = m00 + 24;

    float emA[8], emB[8];
    {
        const float* q0 = pn0 + (size_t)1 * NS;
        const float* q1 = pn1 + (size_t)1 * NS;
        emA[0] = q0[m00]; emA[1] = q1[m00]; emA[2] = q0[m01]; emA[3] = q1[m01];
        emA[4] = q0[m10]; emA[5] = q1[m10]; emA[6] = q0[m11]; emA[7] = q1[m11];
    }
    {
        const float* q0 = pn0 + (size_t)2 * NS;
        const float* q1 = pn1 + (size_t)2 * NS;
        emB[0] = q0[m00]; emB[1] = q1[m00]; emB[2] = q0[m01]; emB[3] = q1[m01];
        emB[4] = q0[m10]; emB[5] = q1[m10]; emB[6] = q0[m11]; emB[7] = q1[m11];
    }

    int ksum0 = 0, ksum1 = 0;
    uint32_t cur = 0;
    // epilogue store addresses (physical contiguous span wbase+4*gidr .. +3)
    const uint32_t stoff = (uint32_t)((wbase + 4 * gidr) * 2);

    for (int t = 1; t < TT; t++) {
        const uint32_t bufb = smem_base + SM_EA + cur * EABUF;

        // ---- hoisted: renorm, mask, exp(em) (independent of D) ----
        float ms0 = mslotF[cur * 8 + n0];
        float ms1 = mslotF[cur * 8 + n1];
        uint32_t mw = masksS[t - 1];
        uint32_t e0b = (__float_as_uint(ms0) >> 23) & 0xFFu;
        uint32_t e1b = (__float_as_uint(ms1) >> 23) & 0xFFu;
        ksum0 += (int)e0b - 127;
        ksum1 += (int)e1b - 127;
        float invM0 = __uint_as_float((254u - e0b) << 23);
        float invM1 = __uint_as_float((254u - e1b) << 23);
        float es[8];
#pragma unroll
        for (int i = 0; i < 8; i += 2) {
            es[i]     = __expf(emA[i]) * invM0;
            es[i + 1] = __expf(emA[i + 1]) * invM1;
        }
#pragma unroll
        for (int i = 0; i < 8; i++) emA[i] = emB[i];
        if (t + 2 < TT) {
            const float* q0 = pn0 + (size_t)(t + 2) * NS;
            const float* q1 = pn1 + (size_t)(t + 2) * NS;
            emB[0] = q0[m00]; emB[1] = q1[m00]; emB[2] = q0[m01]; emB[3] = q1[m01];
            emB[4] = q0[m10]; emB[5] = q1[m10]; emB[6] = q0[m11]; emB[7] = q1[m11];
        }

        // ---- MMA: 4 independent accumulator chains (tile x kt-parity) ----
        float d0e[4] = {0.f, 0.f, 0.f, 0.f}, d0o[4] = {0.f, 0.f, 0.f, 0.f};
        float d1e[4] = {0.f, 0.f, 0.f, 0.f}, d1o[4] = {0.f, 0.f, 0.f, 0.f};
        const uint32_t bbase = bufb + (uint32_t)(gidr * RSB + tig * 4);
#pragma unroll
        for (int half = 0; half < 2; half++) {
            uint32_t Bw[16];
#pragma unroll
            for (int k = 0; k < 8; k++) {
                uint32_t ad = bbase + (uint32_t)((half * 8 + k) * 32);
                asm volatile("ld.shared.b32 %0,[%1];" : "=r"(Bw[2 * k]) : "r"(ad));
                asm volatile("ld.shared.b32 %0,[%1];" : "=r"(Bw[2 * k + 1]) : "r"(ad + 16));
            }
#pragma unroll
            for (int k = 0; k < 8; k++) {
                int kt = half * 8 + k;
                if (k & 1) {
                    MMA_BF16(d0o, A[0][kt], Bw[2 * k], Bw[2 * k + 1]);
                    MMA_BF16(d1o, A[1][kt], Bw[2 * k], Bw[2 * k + 1]);
                } else {
                    MMA_BF16(d0e, A[0][kt], Bw[2 * k], Bw[2 * k + 1]);
                    MMA_BF16(d1e, A[1][kt], Bw[2 * k], Bw[2 * k + 1]);
                }
            }
        }

        // rare masked path
        float Sv0 = 0.f, Sv1 = 0.f;
        if (mw != 0xFFu) {
            if (wid < 8) {
                float s = 0.f;
#pragma unroll
                for (int q = 0; q < 4; q++) {
                    uint32_t v;
                    uint32_t ad = bufb + (uint32_t)(wid * RSB + (lane * 4 + q) * 4);
                    asm volatile("ld.shared.b32 %0,[%1];" : "=r"(v) : "r"(ad));
                    s += __uint_as_float(v << 16) + __uint_as_float(v & 0xFFFF0000u);
                }
#pragma unroll
                for (int o = 16; o; o >>= 1) s += __shfl_xor_sync(~0u, s, o);
                if (lane == 0) Ssm[wid] = s;
            }
            __syncthreads();
            Sv0 = Ssm[n0] * invM0;
            Sv1 = Ssm[n1] * invM1;
        }

        // ---- epilogue: u = d*es, pack bf16x2 pairs, 2x STS.64 ----
        const uint32_t nxtb = smem_base + SM_EA + (cur ^ 1u) * EABUF;
        float u00 = (d0e[0] + d0o[0]) * es[0], u01 = (d0e[1] + d0o[1]) * es[1];
        float u02 = (d0e[2] + d0o[2]) * es[2], u03 = (d0e[3] + d0o[3]) * es[3];
        float u10 = (d1e[0] + d1o[0]) * es[4], u11 = (d1e[1] + d1o[1]) * es[5];
        float u12 = (d1e[2] + d1o[2]) * es[6], u13 = (d1e[3] + d1o[3]) * es[7];
        if (mw != 0xFFu) {
            if (!((mw >> n0) & 1u)) { u00 = Sv0; u02 = Sv0; u10 = Sv0; u12 = Sv0; }
            if (!((mw >> n1) & 1u)) { u01 = Sv1; u03 = Sv1; u11 = Sv1; u13 = Sv1; }
        }
        {
            // physical order for this thread: h=0,1,2,3 -> states m00,m01,m10,m11
            uint32_t w0, w1, w2, w3;
            asm volatile("cvt.rn.bf16x2.f32 %0, %1, %2;" : "=r"(w0) : "f"(u02), "f"(u00));
            asm volatile("cvt.rn.bf16x2.f32 %0, %1, %2;" : "=r"(w1) : "f"(u12), "f"(u10));
            asm volatile("cvt.rn.bf16x2.f32 %0, %1, %2;" : "=r"(w2) : "f"(u03), "f"(u01));
            asm volatile("cvt.rn.bf16x2.f32 %0, %1, %2;" : "=r"(w3) : "f"(u13), "f"(u11));
            uint32_t a0 = nxtb + (uint32_t)(n0 * RSB) + stoff;
            uint32_t a1 = nxtb + (uint32_t)(n1 * RSB) + stoff;
            asm volatile("st.shared.v2.b32 [%0], {%1,%2};" :: "r"(a0), "r"(w0), "r"(w1));
            asm volatile("st.shared.v2.b32 [%0], {%1,%2};" :: "r"(a1), "r"(w2), "r"(w3));
        }
        if (tid < 4) {  // warp0 gidr==0: state 0 = u00/u01
            mslotF[(cur ^ 1u) * 8 + n0] = u00;
            mslotF[(cur ^ 1u) * 8 + n1] = u01;
        }
        __syncthreads();
        cur ^= 1u;
    }

    // epilogue: den[b] = C0 + ksum*ln2 + log(sum ea[perm(tid)] * exp(trans[STOP, perm(tid)]))
    {
        int st = permf(tid);
        float ets = __expf(trans[STOP_TAG * NS + st]);
        const uint32_t bufb = smem_base + SM_EA + cur * EABUF;
        float v[NB];
#pragma unroll
        for (int n = 0; n < NB; n++) {
            uint32_t hv;
            uint32_t ad = bufb + (uint32_t)(n * RSB + tid * 2);
            asm volatile("ld.shared.u16 %0,[%1];" : "=r"(hv) : "r"(ad));
            v[n] = __uint_as_float(hv << 16) * ets;
        }
#pragma unroll
        for (int n = 0; n < NB; n++) {
            float s = v[n];
#pragma unroll
            for (int o = 16; o; o >>= 1) s += __shfl_xor_sync(~0u, s, o);
            if (lane == 0) redsm[wid * 8 + n] = s;
        }
        if (tid < 4) { kssm[n0] = ksum0; kssm[n1] = ksum1; }
        __syncthreads();
        if (tid < 8) {
            float s = 0.f;
#pragma unroll
            for (int w = 0; w < 8; w++) s += redsm[w * 8 + tid];
            g_den[bb + tid] = C0sm[tid] + (float)kssm[tid] * LN2F + __logf(s);
        }
    }
}

// ---------------------------------------------------------------------------
// Numerator: 1 warp per batch
// ---------------------------------------------------------------------------
__global__ void num_kernel(const float* __restrict__ inputs,
                           const float* __restrict__ trans,
                           const int* __restrict__ tags,
                           const int* __restrict__ mask)
{
    int b = blockIdx.x;
    int lane = threadIdx.x;
    const int* tg = tags + b * TT;
    const int* mk = mask + b * TT;
    float sc = 0.f;
    int mc = 0;
    for (int t = lane; t < TT; t += 32) {
        int tgt = tg[t];
        int m = mk[t];
        mc += m;
        if (t >= 1) sc += trans[tgt * NS + tg[t - 1]] * (float)m;
        if (t < TT - 1) sc += inputs[((size_t)b * TT + t) * NS + tgt] * (float)m;
    }
#pragma unroll
    for (int o = 16; o; o >>= 1) {
        sc += __shfl_xor_sync(0xffffffffu, sc, o);
        mc += __shfl_xor_sync(0xffffffffu, mc, o);
    }
    if (lane == 0) {
        sc += trans[tg[0] * NS + START_TAG];
        int li = mc - 1;
        if (li < 0) li = 0;
        int lt = tg[li];
        sc += trans[STOP_TAG * NS + lt]
            + inputs[((size_t)b * TT + (TT - 1)) * NS + lt] * (float)mk[TT - 1];
        g_num[b] = sc;
    }
}

// ---------------------------------------------------------------------------
// Final reduce: sum_b (num - den)
// ---------------------------------------------------------------------------
__global__ void final_kernel(float* __restrict__ out)
{
    __shared__ float red[8];
    int tid = threadIdx.x;
    int lane = tid & 31, wid = tid >> 5;
    float v = g_num[tid] - g_den[tid];
#pragma unroll
    for (int o = 16; o; o >>= 1) v += __shfl_xor_sync(0xffffffffu, v, o);
    if (lane == 0) red[wid] = v;
    __syncthreads();
    if (tid == 0) {
        float s = 0.f;
#pragma unroll
        for (int w = 0; w < 8; w++) s += red[w];
        out[0] = s;
    }
}

extern "C" void kernel_launch(void* const* d_in, const int* in_sizes, int n_in,
                              void* d_out, int out_size)
{
    const float* inputs = (const float*)d_in[0];
    const float* trans  = (const float*)d_in[1];
    const int*   tags   = (const int*)d_in[2];
    const int*   mask   = (const int*)d_in[3];

    prep_kernel<<<256, 256>>>(trans);
    forward_kernel<<<NCTA, 256>>>(inputs, trans, mask);
    num_kernel<<<BB, 32>>>(inputs, trans, tags, mask);
    final_kernel<<<1, 256>>>((float*)d_out);
}